// round 2
// baseline (speedup 1.0000x reference)
#include <cuda_runtime.h>
#include <cuda_bf16.h>
#include <math.h>

// Problem: p1,p2 [8,64,128,128] f32 -> 4x4 avgpool -> rows [8192,64] L2-normalized
// loss = mean((Xa Xa^T - Xb Xb^T)^2) = (||Caa||^2 + ||Cbb||^2 - 2||Cab||^2)/N^2
// with Caa = Xa^T Xa etc (64x64).

#define NROWS 8192
#define NCH   64
#define RT    64              // rows per cov tile
#define NBLK  (NROWS / RT)    // 128 cov blocks
#define SPAD  68              // smem pitch (floats); swizzle uses offsets up to 67
#define NC2   (NCH * NCH)     // 4096

// Scratch (__device__ globals: allocation-free rule)
__device__ float g_X[2][NROWS][NCH];              // normalized pooled rows, row-major
__device__ float g_part[NBLK * 3 * NC2];          // per-block covariance partials
__device__ float g_red[3 * NC2];                  // signed squares

// 16B-granular bank swizzle: add 4 floats when offset >= 32 floats.
// Maps the 8 j-chunks {0,8,...,56} onto 8 distinct 4-bank groups.
__device__ __forceinline__ int swz(int o) { return o + ((o & 32) >> 3); }

__device__ __forceinline__ unsigned long long dup2(float x) {
    unsigned long long r;
    asm("mov.b64 %0, {%1, %1};" : "=l"(r) : "f"(x));
    return r;
}
__device__ __forceinline__ void fma2(unsigned long long& d,
                                     unsigned long long a, unsigned long long b) {
    asm("fma.rn.f32x2 %0, %1, %2, %0;" : "+l"(d) : "l"(a), "l"(b));
}

// ---------------------------------------------------------------------------
// K1: fused 4x4 avg-pool + row L2-normalize.
// One block per (input, b, sh): 256 threads, thread = (c = tid>>2, h = tid&3).
// ---------------------------------------------------------------------------
__global__ void k_pool(const float* __restrict__ p1, const float* __restrict__ p2) {
    __shared__ float sp[NCH][33];    // pooled values [c][sw], odd pitch -> conflict-free
    __shared__ float nrmp[8][32];
    __shared__ float sinv[32];

    int bid   = blockIdx.x;          // 0..511
    int input = bid >> 8;
    int b     = (bid >> 5) & 7;
    int sh    = bid & 31;
    int tid   = threadIdx.x;
    int c     = tid >> 2, h = tid & 3;

    const float* p = input ? p2 : p1;
    const float4* src = reinterpret_cast<const float4*>(
        p + (((size_t)(b * 64 + c) * 128) + (size_t)(4 * sh + h)) * 128);

    // each thread sums its pixel row into 32 per-sw partial sums (high MLP: 32 indep LDG.128)
    float s[32];
#pragma unroll
    for (int g = 0; g < 32; g++) {
        float4 v = src[g];
        s[g] = (v.x + v.y) + (v.z + v.w);
    }
    // reduce across the 4 h-lanes (same warp: lane bits 0..1 are h)
#pragma unroll
    for (int g = 0; g < 32; g++) {
        s[g] += __shfl_xor_sync(0xffffffffu, s[g], 1);
        s[g] += __shfl_xor_sync(0xffffffffu, s[g], 2);
    }
    if (h == 0) {
#pragma unroll
        for (int g = 0; g < 32; g++)
            sp[c][g] = s[g] * 0.0625f;   // mean over 16 pixels
    }
    __syncthreads();

    // row norms: 8 groups of 8 channels per sw
    {
        int sw = tid & 31, grp = tid >> 5;
        float ss = 0.f;
#pragma unroll
        for (int i = 0; i < 8; i++) {
            float v = sp[grp * 8 + i][sw];
            ss = fmaf(v, v, ss);
        }
        nrmp[grp][sw] = ss;
    }
    __syncthreads();
    if (tid < 32) {
        float ss = 0.f;
#pragma unroll
        for (int i = 0; i < 8; i++) ss += nrmp[i][tid];
        sinv[tid] = 1.f / fmaxf(sqrtf(ss), 1e-8f);   // matches reference eps clamp
    }
    __syncthreads();

    // write normalized rows, row-major [row][c]; consecutive tid -> consecutive c
    int row0 = b * 1024 + sh * 32;
#pragma unroll
    for (int k = tid; k < 2048; k += 256) {
        int cc = k & 63, sw = k >> 6;
        g_X[input][row0 + sw][cc] = sp[cc][sw] * sinv[sw];
    }
}

// ---------------------------------------------------------------------------
// K2: per-tile covariance partials. 128 blocks x 128 threads.
// Thread grid: tx = tid&7 (j, 8 cols of 8), ty = tid>>3 (i, 16 rows of 4).
// f32x2 packed FMA: 48 fma2/thread/row for Caa, Cbb, Cab 4x(4x2) tiles.
// ---------------------------------------------------------------------------
__global__ void k_cov() {
    __shared__ float sA[RT][SPAD];
    __shared__ float sB[RT][SPAD];

    int bid = blockIdx.x, tid = threadIdx.x;
    int row0 = bid * RT;

    // load tile: RT x 16 float4 per matrix, perfectly coalesced, swizzled store
#pragma unroll
    for (int k = tid; k < RT * 16; k += 128) {
        int rl = k >> 4, c4 = (k & 15) * 4;
        float4 va = *reinterpret_cast<const float4*>(&g_X[0][row0 + rl][c4]);
        float4 vb = *reinterpret_cast<const float4*>(&g_X[1][row0 + rl][c4]);
        *reinterpret_cast<float4*>(&sA[rl][swz(c4)]) = va;
        *reinterpret_cast<float4*>(&sB[rl][swz(c4)]) = vb;
    }
    __syncthreads();

    int tx = tid & 7, ty = tid >> 3;
    int i0 = ty * 4, j0 = tx * 8;
    int i0s = swz(i0), j0s = swz(j0), j4s = swz(j0 + 4);

    unsigned long long caa[4][4] = {}, cbb[4][4] = {}, cab[4][4] = {};

    for (int r = 0; r < RT; r++) {
        float4 ai4 = *reinterpret_cast<const float4*>(&sA[r][i0s]);
        float4 bi4 = *reinterpret_cast<const float4*>(&sB[r][i0s]);
        ulonglong2 aj01 = *reinterpret_cast<const ulonglong2*>(&sA[r][j0s]);
        ulonglong2 aj23 = *reinterpret_cast<const ulonglong2*>(&sA[r][j4s]);
        ulonglong2 bj01 = *reinterpret_cast<const ulonglong2*>(&sB[r][j0s]);
        ulonglong2 bj23 = *reinterpret_cast<const ulonglong2*>(&sB[r][j4s]);
        unsigned long long aj[4] = {aj01.x, aj01.y, aj23.x, aj23.y};
        unsigned long long bj[4] = {bj01.x, bj01.y, bj23.x, bj23.y};
        float ai[4] = {ai4.x, ai4.y, ai4.z, ai4.w};
        float bi[4] = {bi4.x, bi4.y, bi4.z, bi4.w};
#pragma unroll
        for (int ii = 0; ii < 4; ii++) {
            unsigned long long ad = dup2(ai[ii]);
            unsigned long long bd = dup2(bi[ii]);
#pragma unroll
            for (int q = 0; q < 4; q++) {
                fma2(caa[ii][q], ad, aj[q]);
                fma2(cbb[ii][q], bd, bj[q]);
                fma2(cab[ii][q], ad, bj[q]);
            }
        }
    }

    // packed pair (j, j+1) == two consecutive floats in memory: store as 16B chunks
    float* base = g_part + (size_t)bid * 3 * NC2;
#pragma unroll
    for (int ii = 0; ii < 4; ii++) {
        int ro = (i0 + ii) * NCH + j0;
        *reinterpret_cast<ulonglong2*>(base + 0 * NC2 + ro)     = make_ulonglong2(caa[ii][0], caa[ii][1]);
        *reinterpret_cast<ulonglong2*>(base + 0 * NC2 + ro + 4) = make_ulonglong2(caa[ii][2], caa[ii][3]);
        *reinterpret_cast<ulonglong2*>(base + 1 * NC2 + ro)     = make_ulonglong2(cbb[ii][0], cbb[ii][1]);
        *reinterpret_cast<ulonglong2*>(base + 1 * NC2 + ro + 4) = make_ulonglong2(cbb[ii][2], cbb[ii][3]);
        *reinterpret_cast<ulonglong2*>(base + 2 * NC2 + ro)     = make_ulonglong2(cab[ii][0], cab[ii][1]);
        *reinterpret_cast<ulonglong2*>(base + 2 * NC2 + ro + 4) = make_ulonglong2(cab[ii][2], cab[ii][3]);
    }
}

// ---------------------------------------------------------------------------
// K3: fold 128 partials per entry, square, apply sign (+1, +1, -2).
// ---------------------------------------------------------------------------
__global__ void k_reduce() {
    int g = blockIdx.x * blockDim.x + threadIdx.x;   // 0..12287
    float s = 0.f;
#pragma unroll 4
    for (int k = 0; k < NBLK; k++)
        s += g_part[(size_t)k * 3 * NC2 + g];
    int m = g >> 12;                                  // 0: Caa, 1: Cbb, 2: Cab
    float v = s * s;
    g_red[g] = (m == 2) ? -2.f * v : v;
}

// ---------------------------------------------------------------------------
// K4: final sum (double) / N^2
// ---------------------------------------------------------------------------
__global__ void k_final(float* __restrict__ out) {
    __shared__ double red[256];
    int tid = threadIdx.x;
    double acc = 0.0;
    for (int i = tid; i < 3 * NC2; i += 256)
        acc += (double)g_red[i];
    red[tid] = acc;
    __syncthreads();
    for (int s = 128; s > 0; s >>= 1) {
        if (tid < s) red[tid] += red[tid + s];
        __syncthreads();
    }
    if (tid == 0)
        out[0] = (float)(red[0] / ((double)NROWS * (double)NROWS));
}

// ---------------------------------------------------------------------------
extern "C" void kernel_launch(void* const* d_in, const int* in_sizes, int n_in,
                              void* d_out, int out_size) {
    const float* p1 = (const float*)d_in[0];
    const float* p2 = (const float*)d_in[1];
    float* out = (float*)d_out;

    k_pool<<<512, 256>>>(p1, p2);        // pool + normalize (HBM-bound, 64 MB)
    k_cov<<<NBLK, 128>>>();              // three 64x64 covariances (FMA-bound)
    k_reduce<<<48, 256>>>();             // fold partials + signed squares
    k_final<<<1, 256>>>(out);            // scalar loss
}

// round 8
// speedup vs baseline: 1.4290x; 1.4290x over previous
#include <cuda_runtime.h>
#include <cuda_bf16.h>
#include <math.h>

// p1,p2 [8,64,128,128] f32 -> 4x4 avgpool -> 8192 rows x 64 ch, L2-normalized.
// loss = (||Caa||F^2 + ||Cbb||F^2 - 2||Cab||F^2) / N^2,  C.. = X^T Y (64x64).
// 2 launches: fused pool+normalize+cov partials (128 persistent blocks, 2 slabs
// each -> single wave, halved partial traffic), then fold+scalar.

#define NROWS 8192
#define NCH   64
#define RT    32              // rows per slab (one (b,sh) slab)
#define NSLAB 256             // total slabs
#define NBLK  128             // k_main blocks (2 slabs each) -> single wave
#define SPAD  68              // smem pitch (floats)
#define NC2   (NCH * NCH)     // 4096
#define NPART (3 * NC2)       // 12288
#define FBLK  48              // finalize blocks (48*256 == NPART)

// Scratch (__device__ globals: allocation-free rule)
__device__ float        g_part[NBLK][NPART];   // per-block covariance partials
__device__ double       g_bsum[FBLK];          // per-block signed-square sums
__device__ unsigned int g_ctr = 0;             // last-block ticket (reset each run)

// 16B-granular offset shift (keeps float4 alignment; consistent across all accesses)
__device__ __forceinline__ int swz(int o) { return o + ((o & 32) >> 3); }

__device__ __forceinline__ unsigned long long dup2(float x) {
    unsigned long long r;
    asm("mov.b64 %0, {%1, %1};" : "=l"(r) : "f"(x));
    return r;
}
__device__ __forceinline__ void fma2(unsigned long long& d,
                                     unsigned long long a, unsigned long long b) {
    asm("fma.rn.f32x2 %0, %1, %2, %0;" : "+l"(d) : "l"(a), "l"(b));
}

// ---------------------------------------------------------------------------
// K1: fused pool + normalize + covariance partials, 2 slabs per block.
// Slab s -> (b = s>>5, sh = s&31): 32 pooled rows (sw = 0..31).
// ---------------------------------------------------------------------------
__global__ void __launch_bounds__(256) k_main(const float* __restrict__ p1,
                                              const float* __restrict__ p2) {
    __shared__ float sA[RT][SPAD];
    __shared__ float sB[RT][SPAD];
    __shared__ float sinv[2][RT];

    int bid = blockIdx.x;
    int tid = threadIdx.x;

    // covariance accumulators carried across both slabs
    int tx = tid & 15, ty = tid >> 4;
    int i0 = ty * 4, j0 = tx * 4;
    int i0s = swz(i0), j0s = swz(j0);
    unsigned long long caa[4][2] = {}, cbb[4][2] = {}, cab[4][2] = {};

#pragma unroll
    for (int half = 0; half < 2; half++) {
        int slab = bid * 2 + half;          // 0..255
        int b  = slab >> 5;
        int sh = slab & 31;

        // ---- pool: thread = (c = tid>>2, h = tid&3), pixel row 4*sh + h ----
        {
            int c = tid >> 2, h = tid & 3;
            size_t base = (((size_t)(b * 64 + c) * 128) + (size_t)(4 * sh + h)) * 128;
            const float4* a4 = reinterpret_cast<const float4*>(p1 + base);
            const float4* b4 = reinterpret_cast<const float4*>(p2 + base);

            float s[32];
#pragma unroll
            for (int g = 0; g < 32; g++) { float4 v = a4[g]; s[g] = (v.x + v.y) + (v.z + v.w); }
#pragma unroll
            for (int g = 0; g < 32; g++) {
                s[g] += __shfl_xor_sync(0xffffffffu, s[g], 1);
                s[g] += __shfl_xor_sync(0xffffffffu, s[g], 2);
            }
            if (h == 0) {
#pragma unroll
                for (int g = 0; g < 32; g++) sA[g][swz(c)] = s[g] * 0.0625f;
            }
#pragma unroll
            for (int g = 0; g < 32; g++) { float4 v = b4[g]; s[g] = (v.x + v.y) + (v.z + v.w); }
#pragma unroll
            for (int g = 0; g < 32; g++) {
                s[g] += __shfl_xor_sync(0xffffffffu, s[g], 1);
                s[g] += __shfl_xor_sync(0xffffffffu, s[g], 2);
            }
            if (h == 0) {
#pragma unroll
                for (int g = 0; g < 32; g++) sB[g][swz(c)] = s[g] * 0.0625f;
            }
        }
        __syncthreads();

        // ---- row L2 norms: (input = tid>>7, row = (tid>>2)&31, q = tid&3) ----
        {
            int input = tid >> 7, row = (tid >> 2) & 31, q = tid & 3;
            const float (*T)[SPAD] = input ? sB : sA;
            float ss = 0.f;
#pragma unroll
            for (int i = 0; i < 16; i++) {
                float v = T[row][swz(q * 16 + i)];
                ss = fmaf(v, v, ss);
            }
            ss += __shfl_xor_sync(0xffffffffu, ss, 1);
            ss += __shfl_xor_sync(0xffffffffu, ss, 2);
            if (q == 0)
                sinv[input][row] = 1.f / fmaxf(sqrtf(ss), 1e-8f);  // reference eps clamp
        }
        __syncthreads();

        // ---- rescale in place ----
#pragma unroll
        for (int k = tid; k < RT * NCH; k += 256) {
            int row = k >> 6, c = k & 63;
            sA[row][swz(c)] *= sinv[0][row];
        }
#pragma unroll
        for (int k = tid; k < RT * NCH; k += 256) {
            int row = k >> 6, c = k & 63;
            sB[row][swz(c)] *= sinv[1][row];
        }
        __syncthreads();

        // ---- covariance accumulate: 16x16 grid, 4(i) x 4(j) x 3 mats ----
#pragma unroll 4
        for (int r = 0; r < RT; r++) {
            float4 ai4 = *reinterpret_cast<const float4*>(&sA[r][i0s]);
            float4 bi4 = *reinterpret_cast<const float4*>(&sB[r][i0s]);
            ulonglong2 aj2 = *reinterpret_cast<const ulonglong2*>(&sA[r][j0s]);
            ulonglong2 bj2 = *reinterpret_cast<const ulonglong2*>(&sB[r][j0s]);
            unsigned long long aj[2] = {aj2.x, aj2.y};
            unsigned long long bj[2] = {bj2.x, bj2.y};
            float ai[4] = {ai4.x, ai4.y, ai4.z, ai4.w};
            float bi[4] = {bi4.x, bi4.y, bi4.z, bi4.w};
#pragma unroll
            for (int ii = 0; ii < 4; ii++) {
                unsigned long long ad = dup2(ai[ii]);
                unsigned long long bd = dup2(bi[ii]);
#pragma unroll
                for (int q = 0; q < 2; q++) {
                    fma2(caa[ii][q], ad, aj[q]);
                    fma2(cbb[ii][q], bd, bj[q]);
                    fma2(cab[ii][q], ad, bj[q]);
                }
            }
        }
        __syncthreads();   // protect smem before next slab's pool overwrites
    }

    // ---- store partials (packed pair == consecutive j floats; 16B stores) ----
    float* base = g_part[bid];
#pragma unroll
    for (int ii = 0; ii < 4; ii++) {
        int ro = (i0 + ii) * NCH + j0;
        *reinterpret_cast<ulonglong2*>(base + 0 * NC2 + ro) = make_ulonglong2(caa[ii][0], caa[ii][1]);
        *reinterpret_cast<ulonglong2*>(base + 1 * NC2 + ro) = make_ulonglong2(cbb[ii][0], cbb[ii][1]);
        *reinterpret_cast<ulonglong2*>(base + 2 * NC2 + ro) = make_ulonglong2(cab[ii][0], cab[ii][1]);
    }
}

// ---------------------------------------------------------------------------
// K2: fold 128 partials per entry (two independent chains for MLP), signed
//     square, hierarchical sum, last-block-done scalar emit (deterministic,
//     graph-replay-safe: ticket self-resets).
// ---------------------------------------------------------------------------
__global__ void __launch_bounds__(256) k_fin(float* __restrict__ out) {
    __shared__ double red[256];
    int tid = threadIdx.x;
    int g = blockIdx.x * 256 + tid;          // 0..12287, coalesced across k

    const float* __restrict__ part = &g_part[0][0];
    float s0 = 0.f, s1 = 0.f;
#pragma unroll 8
    for (int k = 0; k < NBLK / 2; k++) {
        s0 += part[(size_t)k * NPART + g];
        s1 += part[(size_t)(k + NBLK / 2) * NPART + g];
    }
    float s = s0 + s1;

    double v = (double)s * (double)s;
    if (g >= 2 * NC2) v = -2.0 * v;          // Cab gets -2

    red[tid] = v;
    __syncthreads();
#pragma unroll
    for (int st = 128; st > 0; st >>= 1) {
        if (tid < st) red[tid] += red[tid + st];
        __syncthreads();
    }

    if (tid == 0) {
        g_bsum[blockIdx.x] = red[0];
        __threadfence();
        unsigned int ticket = atomicAdd(&g_ctr, 1u);
        if (ticket == FBLK - 1) {
            __threadfence();                 // acquire all g_bsum writes
            double tot = 0.0;
            for (int i = 0; i < FBLK; i++) tot += g_bsum[i];
            out[0] = (float)(tot / ((double)NROWS * (double)NROWS));
            g_ctr = 0;                       // reset for next graph replay
        }
    }
}

// ---------------------------------------------------------------------------
extern "C" void kernel_launch(void* const* d_in, const int* in_sizes, int n_in,
                              void* d_out, int out_size) {
    const float* p1 = (const float*)d_in[0];
    const float* p2 = (const float*)d_in[1];
    float* out = (float*)d_out;

    k_main<<<NBLK, 256>>>(p1, p2);   // pool + normalize + cov partials (HBM-bound)
    k_fin<<<FBLK, 256>>>(out);       // fold + signed squares + scalar
}